// round 14
// baseline (speedup 1.0000x reference)
#include <cuda_runtime.h>
#include <cuda_bf16.h>

#define N_CTRL 64
#define N_EVAL 2001
#define DEG 3
#define INV_INTERNAL (1.0f / 61.0f)   // internal knots at k/61

#define TPB 256
#define U_TILE 8
#define VSPLIT 4
#define VCHUNK 501                    // ceil(2001/4)
#define KITER 2                       // ceil(VCHUNK / TPB)
#define ROWF (N_CTRL * 3)             // 192 floats per cp row
#define WIN 8                         // cached cp rows per block
#define STAGE_F 772                   // 768 data floats + 4 pad slack (16B mult)

__device__ __forceinline__ float knotf(int j) {
    if (j <= DEG) return 0.0f;
    if (j >= N_CTRL) return 1.0f;
    return (float)(j - DEG) * INV_INTERNAL;
}

// span = clip(searchsorted(knots, t, 'right') - 1, p, n_ctrl-1), analytic
__device__ __forceinline__ int find_span(float t) {
    int k = (int)floorf(t * 61.0f);
    if (k < 0) k = 0;
    if (k > 60) k = 60;
    if (k < 60 && (float)(k + 1) * INV_INTERNAL <= t) ++k;
    if (k > 0  && (float)k * INV_INTERNAL > t)        --k;
    return DEG + k;
}

// Cox-de-Boor (NURBS book A2.2), p=3, fast division (rel err ~5e-7/weight)
__device__ __forceinline__ void basis_funcs_fast(float u, int span, float N[4]) {
    float left[4], right[4];
    N[0] = 1.0f;
    #pragma unroll
    for (int j = 1; j <= DEG; ++j) {
        left[j]  = u - knotf(span + 1 - j);
        right[j] = knotf(span + j) - u;
        float saved = 0.0f;
        #pragma unroll
        for (int r = 0; r < j; ++r) {
            float temp = __fdividef(N[r], right[r + 1] + left[j - r]);
            N[r] = saved + right[r + 1] * temp;
            saved = left[j - r] * temp;
        }
        N[j] = saved;
    }
}

// v-basis: closed-form uniform cubic for interior spans; Cox-de-Boor fallback
// at the clamped ends.
__device__ __forceinline__ void basis_v(float v, int span, float B[4]) {
    if (span >= 5 && span <= 61) {
        float t  = v * 61.0f - (float)(span - DEG);   // in [0,1)
        float s  = 1.0f - t;
        float t2 = t * t;
        float t3 = t2 * t;
        B[0] = s * s * s * (1.0f / 6.0f);
        B[3] = t3 * (1.0f / 6.0f);
        B[1] = 0.5f * t3 - t2 + (2.0f / 3.0f);
        B[2] = 1.0f - B[0] - B[1] - B[3];             // partition of unity
    } else {
        basis_funcs_fast(v, span, B);
    }
}

// prologue cp-window and main-loop stage buffer never live simultaneously
union SmemU {
    float cp[WIN * ROWF];                // 6 KB   (prologue only)
    float stage[U_TILE][STAGE_F];        // 24.7 KB (main loop only)
};

// ---------------- single fused kernel ----------------
__global__ __launch_bounds__(TPB) void nurbs_kernel(const float* __restrict__ cp,
                                                    const float* __restrict__ pu,
                                                    const float* __restrict__ pv,
                                                    float* __restrict__ out) {
    __shared__ float4 s_curve[U_TILE][N_CTRL];   // 8 KB collapsed curves
    __shared__ SmemU  s_u;                       // 24.7 KB union

    const int u0  = blockIdx.y * U_TILE;
    const int tid = threadIdx.x;
    const int nrows  = (N_EVAL - u0) < U_TILE ? (N_EVAL - u0) : U_TILE;
    const int vstart = blockIdx.x * VCHUNK;
    const int vend   = (vstart + VCHUNK) < N_EVAL ? (vstart + VCHUNK) : N_EVAL;

    // ---- window base: redundant per-thread compute (no phase) ----
    const int s0 = find_span(pu[u0]);            // broadcast LDG
    int lo = s0 - DEG;
    if (lo > N_CTRL - WIN) lo = N_CTRL - WIN;    // clamp to [0, 56]

    // ---- coalesced cache of 8 cp rows: 384 float4 ----
    {
        const float4* src = (const float4*)(cp + lo * ROWF);
        float4* dst = (float4*)s_u.cp;
        #pragma unroll
        for (int i = 0; i < 2; ++i) {
            int idx = tid + i * TPB;
            if (idx < (WIN * ROWF) / 4) dst[idx] = src[idx];
        }
    }
    __syncthreads();

    // ---- u-collapse from smem; 512 items, 2 per thread ----
    #pragma unroll
    for (int it = 0; it < 2; ++it) {
        const int item = tid + it * TPB;
        const int r = item >> 6;
        const int j = item & 63;
        if (r < nrows) {
            const float uu = pu[u0 + r];
            const int   su = find_span(uu);
            float B[4];
            basis_funcs_fast(uu, su, B);
            const int bt = su - DEG - lo;
            float cx = 0.f, cy = 0.f, cz = 0.f;
            if (bt >= 0 && bt + 3 < WIN) {        // warp-uniform pure LDS path
                const float* q0 = s_u.cp + bt * ROWF + j * 3;
                #pragma unroll
                for (int a = 0; a < 4; ++a) {
                    const float* q = q0 + a * ROWF;
                    cx += B[a] * q[0];
                    cy += B[a] * q[1];
                    cz += B[a] * q[2];
                }
            } else {                              // fallback (never for linspace)
                const float* g0 = cp + (su - DEG) * ROWF + j * 3;
                #pragma unroll
                for (int a = 0; a < 4; ++a) {
                    const float* q = g0 + a * ROWF;
                    cx += B[a] * q[0];
                    cy += B[a] * q[1];
                    cz += B[a] * q[2];
                }
            }
            s_curve[r][j] = make_float4(cx, cy, cz, 0.f);
        }
    }
    __syncthreads();   // also separates s_u.cp reads from s_u.stage writes

    // ---- batched pv loads ----
    float pvv[KITER];
    #pragma unroll
    for (int k = 0; k < KITER; ++k) {
        int p  = vstart + k * TPB + tid;
        int pc = p < vend ? p : vend - 1;
        pvv[k] = pv[pc];
    }

    // ---- main: compute -> stage (pad-shifted) -> coalesced aligned drain ----
    #pragma unroll
    for (int k = 0; k < KITER; ++k) {
        if (k > 0) __syncthreads();               // stage buffer reuse
        const int pstart = vstart + k * TPB;
        const int npts   = (vend - pstart) < TPB ? (vend - pstart) : TPB;

        if (tid < npts) {
            const int sv = find_span(pvv[k]);
            float B[4];
            basis_v(pvv[k], sv, B);
            const int o = sv - DEG;
            #pragma unroll
            for (int r = 0; r < U_TILE; ++r) {
                if (r < nrows) {
                    const float4 c0 = s_curve[r][o + 0];
                    const float4 c1 = s_curve[r][o + 1];
                    const float4 c2 = s_curve[r][o + 2];
                    const float4 c3 = s_curve[r][o + 3];
                    float x = B[0] * c0.x + B[1] * c1.x + B[2] * c2.x + B[3] * c3.x;
                    float y = B[0] * c0.y + B[1] * c1.y + B[2] * c2.y + B[3] * c3.y;
                    float z = B[0] * c0.z + B[1] * c1.z + B[2] * c2.z + B[3] * c3.z;
                    // pad = gmem float base & 3 (k-invariant: 256*3 % 4 == 0)
                    const int pad = (3 * (u0 + r + vstart)) & 3;
                    float* st = s_u.stage[r] + pad + tid * 3;
                    st[0] = x;
                    st[1] = y;
                    st[2] = z;
                }
            }
        }
        __syncthreads();

        // drain: 32 lanes per row; aligned float4 body + scalar head/tail
        {
            const int r    = tid >> 5;
            const int lane = tid & 31;
            if (r < nrows) {
                const size_t base = ((size_t)(u0 + r) * N_EVAL + pstart) * 3;
                const int pad = (int)(base & 3);
                const int len = npts * 3;
                float* dst = out + base - pad;            // dst[j] ~ gmem base-pad+j
                const float* src = s_u.stage[r];          // data at src[pad..pad+len)
                const int j0 = (pad + 3) & ~3;
                const int j1 = (pad + len) & ~3;
                if (lane < j0 - pad) dst[pad + lane] = src[pad + lane];       // head <=3
                #pragma unroll 6
                for (int j = j0 + 4 * lane; j < j1; j += 128) {
                    *(float4*)(dst + j) = *(const float4*)(src + j);
                }
                if (lane < pad + len - j1) dst[j1 + lane] = src[j1 + lane];   // tail <=3
            }
        }
    }
}

extern "C" void kernel_launch(void* const* d_in, const int* in_sizes, int n_in,
                              void* d_out, int out_size) {
    const float* cp = (const float*)d_in[0];   // [64,64,3]
    const float* pu = (const float*)d_in[1];   // [2001]
    const float* pv = (const float*)d_in[2];   // [2001]
    float* out = (float*)d_out;

    dim3 grid(VSPLIT, (N_EVAL + U_TILE - 1) / U_TILE);   // (4, 251)
    nurbs_kernel<<<grid, TPB>>>(cp, pu, pv, out);
}

// round 15
// speedup vs baseline: 1.1799x; 1.1799x over previous
#include <cuda_runtime.h>
#include <cuda_bf16.h>

#define N_CTRL 64
#define N_EVAL 2001
#define DEG 3
#define INV_INTERNAL (1.0f / 61.0f)   // internal knots at k/61

#define TPB 256
#define U_TILE 8
#define VSPLIT 4
#define VCHUNK 501                    // ceil(2001/4)
#define KITER 2                       // ceil(VCHUNK / TPB)
#define ROWF (N_CTRL * 3)             // 192 floats per cp row
#define WIN 8                         // cached cp rows per block

// ---- packed f32x2 helpers (sm_103a FFMA2 via PTX) ----
__device__ __forceinline__ unsigned long long pack2(float x, float y) {
    unsigned long long d;
    asm("mov.b64 %0, {%1, %2};" : "=l"(d) : "f"(x), "f"(y));
    return d;
}
__device__ __forceinline__ void unpack2(unsigned long long d, float& x, float& y) {
    asm("mov.b64 {%0, %1}, %2;" : "=f"(x), "=f"(y) : "l"(d));
}
__device__ __forceinline__ unsigned long long fma2(unsigned long long a,
                                                   unsigned long long b,
                                                   unsigned long long c) {
    unsigned long long d;
    asm("fma.rn.f32x2 %0, %1, %2, %3;" : "=l"(d) : "l"(a), "l"(b), "l"(c));
    return d;
}

__device__ __forceinline__ float knotf(int j) {
    if (j <= DEG) return 0.0f;
    if (j >= N_CTRL) return 1.0f;
    return (float)(j - DEG) * INV_INTERNAL;
}

// span = clip(searchsorted(knots, t, 'right') - 1, p, n_ctrl-1), analytic
__device__ __forceinline__ int find_span(float t) {
    int k = (int)floorf(t * 61.0f);
    if (k < 0) k = 0;
    if (k > 60) k = 60;
    if (k < 60 && (float)(k + 1) * INV_INTERNAL <= t) ++k;
    if (k > 0  && (float)k * INV_INTERNAL > t)        --k;
    return DEG + k;
}

// Cox-de-Boor (NURBS book A2.2), p=3, fast division (rel err ~5e-7/weight)
__device__ __forceinline__ void basis_funcs_fast(float u, int span, float N[4]) {
    float left[4], right[4];
    N[0] = 1.0f;
    #pragma unroll
    for (int j = 1; j <= DEG; ++j) {
        left[j]  = u - knotf(span + 1 - j);
        right[j] = knotf(span + j) - u;
        float saved = 0.0f;
        #pragma unroll
        for (int r = 0; r < j; ++r) {
            float temp = __fdividef(N[r], right[r + 1] + left[j - r]);
            N[r] = saved + right[r + 1] * temp;
            saved = left[j - r] * temp;
        }
        N[j] = saved;
    }
}

// v-basis: closed-form uniform cubic for interior spans; Cox-de-Boor fallback
// at the clamped ends.
__device__ __forceinline__ void basis_v(float v, int span, float B[4]) {
    if (span >= 5 && span <= 61) {
        float t  = v * 61.0f - (float)(span - DEG);   // in [0,1)
        float s  = 1.0f - t;
        float t2 = t * t;
        float t3 = t2 * t;
        B[0] = s * s * s * (1.0f / 6.0f);
        B[3] = t3 * (1.0f / 6.0f);
        B[1] = 0.5f * t3 - t2 + (2.0f / 3.0f);
        B[2] = 1.0f - B[0] - B[1] - B[3];             // partition of unity
    } else {
        basis_funcs_fast(v, span, B);
    }
}

// ---------------- single fused kernel (R13 skeleton) ----------------
__global__ __launch_bounds__(TPB) void nurbs_kernel(const float* __restrict__ cp,
                                                    const float* __restrict__ pu,
                                                    const float* __restrict__ pv,
                                                    float* __restrict__ out) {
    __shared__ float4 s_curve[U_TILE][N_CTRL];   // 8 KB collapsed curves (w = 0)
    __shared__ float  s_cp[WIN * ROWF];          // 6 KB cached cp window

    const int u0  = blockIdx.y * U_TILE;
    const int tid = threadIdx.x;
    const int nrows  = (N_EVAL - u0) < U_TILE ? (N_EVAL - u0) : U_TILE;
    const int vstart = blockIdx.x * VCHUNK;
    const int vend   = (vstart + VCHUNK) < N_EVAL ? (vstart + VCHUNK) : N_EVAL;

    // ---- window base: redundant per-thread compute (no phase) ----
    const int s0 = find_span(pu[u0]);            // broadcast LDG
    int lo = s0 - DEG;
    if (lo > N_CTRL - WIN) lo = N_CTRL - WIN;    // clamp to [0, 56]

    // ---- coalesced cache of 8 cp rows: 384 float4 ----
    {
        const float4* src = (const float4*)(cp + lo * ROWF);
        float4* dst = (float4*)s_cp;
        #pragma unroll
        for (int i = 0; i < 2; ++i) {
            int idx = tid + i * TPB;
            if (idx < (WIN * ROWF) / 4) dst[idx] = src[idx];
        }
    }
    __syncthreads();

    // ---- u-collapse from smem; 512 items, 2 per thread ----
    #pragma unroll
    for (int it = 0; it < 2; ++it) {
        const int item = tid + it * TPB;
        const int r = item >> 6;
        const int j = item & 63;
        if (r < nrows) {
            const float uu = pu[u0 + r];
            const int   su = find_span(uu);
            float B[4];
            basis_funcs_fast(uu, su, B);
            const int bt = su - DEG - lo;
            float cx = 0.f, cy = 0.f, cz = 0.f;
            if (bt >= 0 && bt + 3 < WIN) {        // warp-uniform pure LDS path
                const float* q0 = s_cp + bt * ROWF + j * 3;
                #pragma unroll
                for (int a = 0; a < 4; ++a) {
                    const float* q = q0 + a * ROWF;
                    cx += B[a] * q[0];
                    cy += B[a] * q[1];
                    cz += B[a] * q[2];
                }
            } else {                              // fallback (never for linspace)
                const float* g0 = cp + (su - DEG) * ROWF + j * 3;
                #pragma unroll
                for (int a = 0; a < 4; ++a) {
                    const float* q = g0 + a * ROWF;
                    cx += B[a] * q[0];
                    cy += B[a] * q[1];
                    cz += B[a] * q[2];
                }
            }
            s_curve[r][j] = make_float4(cx, cy, cz, 0.f);   // w = 0 (used by f32x2 zw)
        }
    }
    __syncthreads();

    // ---- batched pv loads ----
    float pvv[KITER];
    #pragma unroll
    for (int k = 0; k < KITER; ++k) {
        int p  = vstart + k * TPB + tid;
        int pc = p < vend ? p : vend - 1;
        pvv[k] = pv[pc];
    }

    const bool full_rows = (nrows == U_TILE);

    // ---- main: closed-form v-basis, packed f32x2 accumulation, direct stores ----
    #pragma unroll
    for (int k = 0; k < KITER; ++k) {
        const int p = vstart + k * TPB + tid;
        if (p < vend) {
            const int sv = find_span(pvv[k]);
            float B[4];
            basis_v(pvv[k], sv, B);
            const int o = sv - DEG;
            const unsigned long long Bd0 = pack2(B[0], B[0]);
            const unsigned long long Bd1 = pack2(B[1], B[1]);
            const unsigned long long Bd2 = pack2(B[2], B[2]);
            const unsigned long long Bd3 = pack2(B[3], B[3]);
            float* dst = out + ((size_t)u0 * N_EVAL + p) * 3;

            if (full_rows) {
                #pragma unroll
                for (int r = 0; r < U_TILE; ++r) {
                    const ulonglong2* c =
                        reinterpret_cast<const ulonglong2*>(&s_curve[r][o]);
                    const ulonglong2 q0 = c[0];
                    const ulonglong2 q1 = c[1];
                    const ulonglong2 q2 = c[2];
                    const ulonglong2 q3 = c[3];
                    unsigned long long axy =
                        fma2(Bd3, q3.x, fma2(Bd2, q2.x, fma2(Bd1, q1.x, fma2(Bd0, q0.x, 0ull))));
                    unsigned long long azw =
                        fma2(Bd3, q3.y, fma2(Bd2, q2.y, fma2(Bd1, q1.y, fma2(Bd0, q0.y, 0ull))));
                    float x, y, z, wj;
                    unpack2(axy, x, y);
                    unpack2(azw, z, wj);
                    dst[0] = x;
                    dst[1] = y;
                    dst[2] = z;
                    dst += (size_t)N_EVAL * 3;
                }
            } else {
                #pragma unroll
                for (int r = 0; r < U_TILE; ++r) {
                    if (r < nrows) {
                        const ulonglong2* c =
                            reinterpret_cast<const ulonglong2*>(&s_curve[r][o]);
                        const ulonglong2 q0 = c[0];
                        const ulonglong2 q1 = c[1];
                        const ulonglong2 q2 = c[2];
                        const ulonglong2 q3 = c[3];
                        unsigned long long axy =
                            fma2(Bd3, q3.x, fma2(Bd2, q2.x, fma2(Bd1, q1.x, fma2(Bd0, q0.x, 0ull))));
                        unsigned long long azw =
                            fma2(Bd3, q3.y, fma2(Bd2, q2.y, fma2(Bd1, q1.y, fma2(Bd0, q0.y, 0ull))));
                        float x, y, z, wj;
                        unpack2(axy, x, y);
                        unpack2(azw, z, wj);
                        dst[0] = x;
                        dst[1] = y;
                        dst[2] = z;
                    }
                    dst += (size_t)N_EVAL * 3;
                }
            }
        }
    }
}

extern "C" void kernel_launch(void* const* d_in, const int* in_sizes, int n_in,
                              void* d_out, int out_size) {
    const float* cp = (const float*)d_in[0];   // [64,64,3]
    const float* pu = (const float*)d_in[1];   // [2001]
    const float* pv = (const float*)d_in[2];   // [2001]
    float* out = (float*)d_out;

    dim3 grid(VSPLIT, (N_EVAL + U_TILE - 1) / U_TILE);   // (4, 251)
    nurbs_kernel<<<grid, TPB>>>(cp, pu, pv, out);
}

// round 16
// speedup vs baseline: 1.1844x; 1.0038x over previous
#include <cuda_runtime.h>
#include <cuda_bf16.h>

#define N_CTRL 64
#define N_EVAL 2001
#define DEG 3
#define INV_INTERNAL (1.0f / 61.0f)   // internal knots at k/61

#define TPB 256
#define U_TILE 8
#define VSPLIT 4
#define VCHUNK 501                    // ceil(2001/4)
#define KITER 2                       // ceil(VCHUNK / TPB)
#define ROWF (N_CTRL * 3)             // 192 floats per cp row
#define WIN 8                         // cached cp rows per block

__device__ __forceinline__ float knotf(int j) {
    if (j <= DEG) return 0.0f;
    if (j >= N_CTRL) return 1.0f;
    return (float)(j - DEG) * INV_INTERNAL;
}

// span = clip(searchsorted(knots, t, 'right') - 1, p, n_ctrl-1), analytic
__device__ __forceinline__ int find_span(float t) {
    int k = (int)floorf(t * 61.0f);
    if (k < 0) k = 0;
    if (k > 60) k = 60;
    if (k < 60 && (float)(k + 1) * INV_INTERNAL <= t) ++k;
    if (k > 0  && (float)k * INV_INTERNAL > t)        --k;
    return DEG + k;
}

// Cox-de-Boor (NURBS book A2.2), p=3, fast division (rel err ~5e-7/weight)
__device__ __forceinline__ void basis_funcs_fast(float u, int span, float N[4]) {
    float left[4], right[4];
    N[0] = 1.0f;
    #pragma unroll
    for (int j = 1; j <= DEG; ++j) {
        left[j]  = u - knotf(span + 1 - j);
        right[j] = knotf(span + j) - u;
        float saved = 0.0f;
        #pragma unroll
        for (int r = 0; r < j; ++r) {
            float temp = __fdividef(N[r], right[r + 1] + left[j - r]);
            N[r] = saved + right[r + 1] * temp;
            saved = left[j - r] * temp;
        }
        N[j] = saved;
    }
}

// v-basis: closed-form uniform cubic for interior spans; Cox-de-Boor fallback
// at the clamped ends.
__device__ __forceinline__ void basis_v(float v, int span, float B[4]) {
    if (span >= 5 && span <= 61) {
        float t  = v * 61.0f - (float)(span - DEG);   // in [0,1)
        float s  = 1.0f - t;
        float t2 = t * t;
        float t3 = t2 * t;
        B[0] = s * s * s * (1.0f / 6.0f);
        B[3] = t3 * (1.0f / 6.0f);
        B[1] = 0.5f * t3 - t2 + (2.0f / 3.0f);
        B[2] = 1.0f - B[0] - B[1] - B[3];             // partition of unity
    } else {
        basis_funcs_fast(v, span, B);
    }
}

// one row's v-contraction: scalar FFMA, 3 independent accumulation chains
__device__ __forceinline__ void eval_row(const float4* __restrict__ crow, int o,
                                         const float B[4], float* __restrict__ dst) {
    const float4 c0 = crow[o + 0];
    const float4 c1 = crow[o + 1];
    const float4 c2 = crow[o + 2];
    const float4 c3 = crow[o + 3];
    float x = B[0] * c0.x + B[1] * c1.x + B[2] * c2.x + B[3] * c3.x;
    float y = B[0] * c0.y + B[1] * c1.y + B[2] * c2.y + B[3] * c3.y;
    float z = B[0] * c0.z + B[1] * c1.z + B[2] * c2.z + B[3] * c3.z;
    dst[0] = x;
    dst[1] = y;
    dst[2] = z;
}

// ---------------- single fused kernel (R13 skeleton) ----------------
__global__ __launch_bounds__(TPB) void nurbs_kernel(const float* __restrict__ cp,
                                                    const float* __restrict__ pu,
                                                    const float* __restrict__ pv,
                                                    float* __restrict__ out) {
    __shared__ float4 s_curve[U_TILE][N_CTRL];   // 8 KB collapsed curves
    __shared__ float  s_cp[WIN * ROWF];          // 6 KB cached cp window

    const int u0  = blockIdx.y * U_TILE;
    const int tid = threadIdx.x;
    const int nrows  = (N_EVAL - u0) < U_TILE ? (N_EVAL - u0) : U_TILE;
    const int vstart = blockIdx.x * VCHUNK;
    const int vend   = (vstart + VCHUNK) < N_EVAL ? (vstart + VCHUNK) : N_EVAL;

    // ---- window base: redundant per-thread compute (no phase) ----
    const int s0 = find_span(pu[u0]);            // broadcast LDG
    int lo = s0 - DEG;
    if (lo > N_CTRL - WIN) lo = N_CTRL - WIN;    // clamp to [0, 56]

    // ---- coalesced cache of 8 cp rows: 384 float4 ----
    {
        const float4* src = (const float4*)(cp + lo * ROWF);
        float4* dst = (float4*)s_cp;
        #pragma unroll
        for (int i = 0; i < 2; ++i) {
            int idx = tid + i * TPB;
            if (idx < (WIN * ROWF) / 4) dst[idx] = src[idx];
        }
    }
    __syncthreads();

    // ---- u-collapse from smem; 512 items, 2 per thread ----
    #pragma unroll
    for (int it = 0; it < 2; ++it) {
        const int item = tid + it * TPB;
        const int r = item >> 6;
        const int j = item & 63;
        if (r < nrows) {
            const float uu = pu[u0 + r];
            const int   su = find_span(uu);
            float B[4];
            basis_funcs_fast(uu, su, B);
            const int bt = su - DEG - lo;
            float cx = 0.f, cy = 0.f, cz = 0.f;
            if (bt >= 0 && bt + 3 < WIN) {        // warp-uniform pure LDS path
                const float* q0 = s_cp + bt * ROWF + j * 3;
                #pragma unroll
                for (int a = 0; a < 4; ++a) {
                    const float* q = q0 + a * ROWF;
                    cx += B[a] * q[0];
                    cy += B[a] * q[1];
                    cz += B[a] * q[2];
                }
            } else {                              // fallback (never for linspace)
                const float* g0 = cp + (su - DEG) * ROWF + j * 3;
                #pragma unroll
                for (int a = 0; a < 4; ++a) {
                    const float* q = g0 + a * ROWF;
                    cx += B[a] * q[0];
                    cy += B[a] * q[1];
                    cz += B[a] * q[2];
                }
            }
            s_curve[r][j] = make_float4(cx, cy, cz, 0.f);
        }
    }
    __syncthreads();

    // ---- batched pv loads ----
    float pvv[KITER];
    #pragma unroll
    for (int k = 0; k < KITER; ++k) {
        int p  = vstart + k * TPB + tid;
        int pc = p < vend ? p : vend - 1;
        pvv[k] = pv[pc];
    }

    const bool full_rows = (nrows == U_TILE);

    // ---- main: closed-form v-basis, 8 rows per point, direct stores ----
    #pragma unroll
    for (int k = 0; k < KITER; ++k) {
        const int p = vstart + k * TPB + tid;
        if (p < vend) {
            const int sv = find_span(pvv[k]);
            float B[4];
            basis_v(pvv[k], sv, B);
            const int o = sv - DEG;
            float* dst = out + ((size_t)u0 * N_EVAL + p) * 3;   // one wide calc/point

            if (full_rows) {
                #pragma unroll
                for (int r = 0; r < U_TILE; ++r) {      // guard-free fast path
                    eval_row(s_curve[r], o, B, dst);
                    dst += (size_t)N_EVAL * 3;          // LEA per row
                }
            } else {
                #pragma unroll
                for (int r = 0; r < U_TILE; ++r) {
                    if (r < nrows) eval_row(s_curve[r], o, B, dst);
                    dst += (size_t)N_EVAL * 3;
                }
            }
        }
    }
}

extern "C" void kernel_launch(void* const* d_in, const int* in_sizes, int n_in,
                              void* d_out, int out_size) {
    const float* cp = (const float*)d_in[0];   // [64,64,3]
    const float* pu = (const float*)d_in[1];   // [2001]
    const float* pv = (const float*)d_in[2];   // [2001]
    float* out = (float*)d_out;

    dim3 grid(VSPLIT, (N_EVAL + U_TILE - 1) / U_TILE);   // (4, 251)
    nurbs_kernel<<<grid, TPB>>>(cp, pu, pv, out);
}

// round 17
// speedup vs baseline: 1.3171x; 1.1121x over previous
#include <cuda_runtime.h>
#include <cuda_bf16.h>

#define N_CTRL 64
#define N_EVAL 2001
#define DEG 3
#define INV_INTERNAL (1.0f / 61.0f)   // internal knots at k/61

#define TPB 256
#define U_TILE 8
#define VSPLIT 4
#define VCHUNK 501                    // ceil(2001/4)
#define KITER 2                       // ceil(VCHUNK / TPB)
#define ROWF (N_CTRL * 3)             // 192 floats per cp row
#define WIN 8                         // cached cp rows per block

__device__ __forceinline__ float knotf(int j) {
    if (j <= DEG) return 0.0f;
    if (j >= N_CTRL) return 1.0f;
    return (float)(j - DEG) * INV_INTERNAL;
}

// span = clip(searchsorted(knots, t, 'right') - 1, p, n_ctrl-1), analytic
__device__ __forceinline__ int find_span(float t) {
    int k = (int)floorf(t * 61.0f);
    if (k < 0) k = 0;
    if (k > 60) k = 60;
    if (k < 60 && (float)(k + 1) * INV_INTERNAL <= t) ++k;
    if (k > 0  && (float)k * INV_INTERNAL > t)        --k;
    return DEG + k;
}

// Cox-de-Boor (NURBS book A2.2), p=3, fast division (rel err ~5e-7/weight)
__device__ __forceinline__ void basis_funcs_fast(float u, int span, float N[4]) {
    float left[4], right[4];
    N[0] = 1.0f;
    #pragma unroll
    for (int j = 1; j <= DEG; ++j) {
        left[j]  = u - knotf(span + 1 - j);
        right[j] = knotf(span + j) - u;
        float saved = 0.0f;
        #pragma unroll
        for (int r = 0; r < j; ++r) {
            float temp = __fdividef(N[r], right[r + 1] + left[j - r]);
            N[r] = saved + right[r + 1] * temp;
            saved = left[j - r] * temp;
        }
        N[j] = saved;
    }
}

// closed-form uniform cubic basis for interior spans (knots j in [3,64] are
// exactly (j-3)/61, so spans 5..61 see purely uniform knots); Cox-de-Boor
// fallback at the clamped ends. Used for BOTH u and v axes.
__device__ __forceinline__ void basis_any(float t_param, int span, float B[4]) {
    if (span >= 5 && span <= 61) {
        float t  = t_param * 61.0f - (float)(span - DEG);   // in [0,1)
        float s  = 1.0f - t;
        float t2 = t * t;
        float t3 = t2 * t;
        B[0] = s * s * s * (1.0f / 6.0f);
        B[3] = t3 * (1.0f / 6.0f);
        B[1] = 0.5f * t3 - t2 + (2.0f / 3.0f);
        B[2] = 1.0f - B[0] - B[1] - B[3];                   // partition of unity
    } else {
        basis_funcs_fast(t_param, span, B);
    }
}

// ---------------- single fused kernel (R13 skeleton, closed-form u-basis) ----------------
__global__ __launch_bounds__(TPB) void nurbs_kernel(const float* __restrict__ cp,
                                                    const float* __restrict__ pu,
                                                    const float* __restrict__ pv,
                                                    float* __restrict__ out) {
    __shared__ float4 s_curve[U_TILE][N_CTRL];   // 8 KB collapsed curves
    __shared__ float  s_cp[WIN * ROWF];          // 6 KB cached cp window

    const int u0  = blockIdx.y * U_TILE;
    const int tid = threadIdx.x;
    const int nrows  = (N_EVAL - u0) < U_TILE ? (N_EVAL - u0) : U_TILE;
    const int vstart = blockIdx.x * VCHUNK;
    const int vend   = (vstart + VCHUNK) < N_EVAL ? (vstart + VCHUNK) : N_EVAL;

    // ---- window base: redundant per-thread compute (no phase) ----
    const int s0 = find_span(pu[u0]);            // broadcast LDG
    int lo = s0 - DEG;
    if (lo > N_CTRL - WIN) lo = N_CTRL - WIN;    // clamp to [0, 56]

    // ---- coalesced cache of 8 cp rows: 384 float4 ----
    {
        const float4* src = (const float4*)(cp + lo * ROWF);
        float4* dst = (float4*)s_cp;
        #pragma unroll
        for (int i = 0; i < 2; ++i) {
            int idx = tid + i * TPB;
            if (idx < (WIN * ROWF) / 4) dst[idx] = src[idx];
        }
    }
    __syncthreads();

    // ---- u-collapse from smem; 512 items, 2 per thread ----
    // closed-form basis (no MUFU chain) on interior spans; exact-form fallback
    // only in the first/last u-blocks.
    #pragma unroll
    for (int it = 0; it < 2; ++it) {
        const int item = tid + it * TPB;
        const int r = item >> 6;
        const int j = item & 63;
        if (r < nrows) {
            const float uu = pu[u0 + r];
            const int   su = find_span(uu);
            float B[4];
            basis_any(uu, su, B);
            const int bt = su - DEG - lo;
            float cx = 0.f, cy = 0.f, cz = 0.f;
            if (bt >= 0 && bt + 3 < WIN) {        // warp-uniform pure LDS path
                const float* q0 = s_cp + bt * ROWF + j * 3;
                #pragma unroll
                for (int a = 0; a < 4; ++a) {
                    const float* q = q0 + a * ROWF;
                    cx += B[a] * q[0];
                    cy += B[a] * q[1];
                    cz += B[a] * q[2];
                }
            } else {                              // fallback (never for linspace)
                const float* g0 = cp + (su - DEG) * ROWF + j * 3;
                #pragma unroll
                for (int a = 0; a < 4; ++a) {
                    const float* q = g0 + a * ROWF;
                    cx += B[a] * q[0];
                    cy += B[a] * q[1];
                    cz += B[a] * q[2];
                }
            }
            s_curve[r][j] = make_float4(cx, cy, cz, 0.f);
        }
    }
    __syncthreads();

    // ---- batched pv loads ----
    float pvv[KITER];
    #pragma unroll
    for (int k = 0; k < KITER; ++k) {
        int p  = vstart + k * TPB + tid;
        int pc = p < vend ? p : vend - 1;
        pvv[k] = pv[pc];
    }

    // ---- main: closed-form v-basis, 8 rows per point, direct stores ----
    // (byte-identical to R13 — proven local optimum; do not touch)
    #pragma unroll
    for (int k = 0; k < KITER; ++k) {
        const int p = vstart + k * TPB + tid;
        if (p < vend) {
            const int sv = find_span(pvv[k]);
            float B[4];
            basis_any(pvv[k], sv, B);
            const int o = sv - DEG;
            #pragma unroll
            for (int r = 0; r < U_TILE; ++r) {
                if (r < nrows) {
                    const float4 c0 = s_curve[r][o + 0];
                    const float4 c1 = s_curve[r][o + 1];
                    const float4 c2 = s_curve[r][o + 2];
                    const float4 c3 = s_curve[r][o + 3];
                    float x = B[0] * c0.x + B[1] * c1.x + B[2] * c2.x + B[3] * c3.x;
                    float y = B[0] * c0.y + B[1] * c1.y + B[2] * c2.y + B[3] * c3.y;
                    float z = B[0] * c0.z + B[1] * c1.z + B[2] * c2.z + B[3] * c3.z;
                    float* dst = out + ((size_t)(u0 + r) * N_EVAL + p) * 3;
                    dst[0] = x;
                    dst[1] = y;
                    dst[2] = z;
                }
            }
        }
    }
}

extern "C" void kernel_launch(void* const* d_in, const int* in_sizes, int n_in,
                              void* d_out, int out_size) {
    const float* cp = (const float*)d_in[0];   // [64,64,3]
    const float* pu = (const float*)d_in[1];   // [2001]
    const float* pv = (const float*)d_in[2];   // [2001]
    float* out = (float*)d_out;

    dim3 grid(VSPLIT, (N_EVAL + U_TILE - 1) / U_TILE);   // (4, 251)
    nurbs_kernel<<<grid, TPB>>>(cp, pu, pv, out);
}